// round 1
// baseline (speedup 1.0000x reference)
#include <cuda_runtime.h>

#define N_SAMP   1024
#define N_COL    128
#define TILE     128
#define N_TILES  8              // 1024 / 128
#define N_TP     36             // 8 + 7 + ... + 1 upper-tri incl diag
#define N_JOBS   (N_TP * N_COL) // 4608

// tile-pair enumeration (ti <= tj)
__constant__ unsigned char c_ti[N_TP] = {
    0,0,0,0,0,0,0,0,
    1,1,1,1,1,1,1,
    2,2,2,2,2,2,
    3,3,3,3,3,
    4,4,4,4,
    5,5,5,
    6,6,
    7
};
__constant__ unsigned char c_tj[N_TP] = {
    0,1,2,3,4,5,6,7,
    1,2,3,4,5,6,7,
    2,3,4,5,6,7,
    3,4,5,6,7,
    4,5,6,7,
    5,6,7,
    6,7,
    7
};

__device__ float g_partial[N_JOBS];

__device__ __forceinline__ float tanh_fast(float x) {
    float r;
    asm("tanh.approx.f32 %0, %1;" : "=f"(r) : "f"(x));
    return r;
}

__global__ __launch_bounds__(TILE) void tau_tiles_kernel(
    const float* __restrict__ pred, const float* __restrict__ y)
{
    const int tp  = blockIdx.x;   // 0..35
    const int col = blockIdx.y;   // 0..127
    const int tid = threadIdx.x;  // 0..127

    const int ti = c_ti[tp];
    const int tj = c_tj[tp];

    const float* pc = pred + col * N_SAMP;
    const float* lc = y    + col * N_SAMP;

    // this thread's i-row values (registers)
    const float pi = pc[ti * TILE + tid];
    const float li = lc[ti * TILE + tid];

    // j-tile into shared memory as float2 (one LDS.64 per inner iter, broadcast)
    __shared__ float2 sj[TILE];
    sj[tid] = make_float2(pc[tj * TILE + tid], lc[tj * TILE + tid]);
    __syncthreads();

    float acc = 0.0f;
#pragma unroll 16
    for (int j = 0; j < TILE; ++j) {
        float2 v  = sj[j];
        float d   = pi - v.x;
        float ld  = li - v.y;
        float t   = tanh_fast(d);
        // sign(ld) in {-1, 0, +1}; tanh(d*s) == s*tanh(d)
        float s   = (float)((ld > 0.0f) - (ld < 0.0f));
        acc = fmaf(t, s, acc);
    }

    // off-diagonal tiles counted once but represent both (i,j) and (j,i)
    if (ti != tj) acc *= 2.0f;

    // block reduction: warp shuffle then cross-warp via shared
    #pragma unroll
    for (int off = 16; off > 0; off >>= 1)
        acc += __shfl_down_sync(0xffffffffu, acc, off);

    __shared__ float warp_sums[TILE / 32];
    if ((tid & 31) == 0) warp_sums[tid >> 5] = acc;
    __syncthreads();

    if (tid == 0) {
        float total = warp_sums[0] + warp_sums[1] + warp_sums[2] + warp_sums[3];
        g_partial[col * N_TP + tp] = total;
    }
}

__global__ __launch_bounds__(256) void tau_finalize_kernel(float* __restrict__ out)
{
    const int tid = threadIdx.x;
    float acc = 0.0f;
    for (int i = tid; i < N_JOBS; i += 256)
        acc += g_partial[i];

    #pragma unroll
    for (int off = 16; off > 0; off >>= 1)
        acc += __shfl_down_sync(0xffffffffu, acc, off);

    __shared__ float warp_sums[8];
    if ((tid & 31) == 0) warp_sums[tid >> 5] = acc;
    __syncthreads();

    if (tid == 0) {
        float total = 0.0f;
        #pragma unroll
        for (int w = 0; w < 8; ++w) total += warp_sums[w];
        // mean over columns of per_col = S_c / (n*(n-1)); result = 1 - mean
        const float norm = (float)N_COL * (float)N_SAMP * (float)(N_SAMP - 1);
        out[0] = 1.0f - total / norm;
    }
}

extern "C" void kernel_launch(void* const* d_in, const int* in_sizes, int n_in,
                              void* d_out, int out_size)
{
    const float* pred = (const float*)d_in[0];
    const float* y    = (const float*)d_in[1];
    float* out        = (float*)d_out;

    dim3 grid(N_TP, N_COL);
    tau_tiles_kernel<<<grid, TILE>>>(pred, y);
    tau_finalize_kernel<<<1, 256>>>(out);
}

// round 4
// speedup vs baseline: 1.4100x; 1.4100x over previous
#include <cuda_runtime.h>

#define N_SAMP   1024
#define N_COL    128
#define TILE     128
#define N_TP     36             // tile-pairs with ti <= tj (8+7+...+1)
#define N_BLOCKS (N_TP * N_COL) // 4608

// tile-pair enumeration (ti <= tj)
__constant__ unsigned char c_ti[N_TP] = {
    0,0,0,0,0,0,0,0,
    1,1,1,1,1,1,1,
    2,2,2,2,2,2,
    3,3,3,3,3,
    4,4,4,4,
    5,5,5,
    6,6,
    7
};
__constant__ unsigned char c_tj[N_TP] = {
    0,1,2,3,4,5,6,7,
    1,2,3,4,5,6,7,
    2,3,4,5,6,7,
    3,4,5,6,7,
    4,5,6,7,
    5,6,7,
    6,7,
    7
};

// Order-independent integer accumulation -> bit-deterministic across replays.
__device__ long long    g_sum;    // zero-initialized at module load; reset by last block
__device__ unsigned int g_count;  // ditto

#define SUM_SCALE 268435456.0    // 2^28

__device__ __forceinline__ float tanh_fast(float x) {
    float r;
    asm("tanh.approx.f32 %0, %1;" : "=f"(r) : "f"(x));
    return r;
}

__global__ __launch_bounds__(TILE) void tau_fused_kernel(
    const float* __restrict__ pred, const float* __restrict__ y,
    float* __restrict__ out)
{
    const int tp  = blockIdx.x;   // 0..35
    const int col = blockIdx.y;   // 0..127
    const int tid = threadIdx.x;  // 0..127

    const int ti = c_ti[tp];
    const int tj = c_tj[tp];

    const float* pc = pred + col * N_SAMP;
    const float* lc = y    + col * N_SAMP;

    // this thread's i-row values (registers)
    const float pi = pc[ti * TILE + tid];
    const float li = lc[ti * TILE + tid];

    // j-tile in shared memory as float2 (LDS.64 broadcast, conflict-free)
    __shared__ float2 sj[TILE];
    sj[tid] = make_float2(pc[tj * TILE + tid], lc[tj * TILE + tid]);
    __syncthreads();

    // Every tile-pair (incl. diagonal) now represents BOTH orderings (weight 2).
    // Diagonal tiles only walk j > tid (tanh is odd: term(i,j)+term(j,i)=2*term(i,j)).
    const int jstart = (ti == tj) ? (tid + 1) : 0;

    float acc = 0.0f;
#pragma unroll 4
    for (int j = jstart; j < TILE; ++j) {
        float2 v  = sj[j];
        float d   = pi - v.x;
        float ld  = li - v.y;
        float t   = tanh_fast(d);
        // t * sign(ld) via sign-bit XOR (single LOP3).
        // ld == 0 only happens together with d == 0 (=> t == 0), so safe.
        unsigned s = __float_as_uint(ld) & 0x80000000u;
        acc += __uint_as_float(__float_as_uint(t) ^ s);
    }
    acc *= 2.0f;

    // block reduction: warp shuffle then cross-warp via shared
    #pragma unroll
    for (int off = 16; off > 0; off >>= 1)
        acc += __shfl_down_sync(0xffffffffu, acc, off);

    __shared__ float warp_sums[TILE / 32];
    if ((tid & 31) == 0) warp_sums[tid >> 5] = acc;
    __syncthreads();

    if (tid == 0) {
        float total = warp_sums[0] + warp_sums[1] + warp_sums[2] + warp_sums[3];

        // deterministic fixed-point accumulation (double for exact scaling)
        long long q = llrint((double)total * SUM_SCALE);
        atomicAdd((unsigned long long*)&g_sum, (unsigned long long)q);
        __threadfence();

        unsigned prev = atomicAdd(&g_count, 1u);
        if (prev == (unsigned)(N_BLOCKS - 1)) {
            // all blocks' g_sum updates are visible (fenced before their count inc)
            __threadfence();
            long long s = *((volatile long long*)&g_sum);
            const double norm = (double)N_COL * (double)N_SAMP * (double)(N_SAMP - 1);
            out[0] = (float)(1.0 - ((double)s / SUM_SCALE) / norm);
            // reset for the next graph replay
            *((volatile long long*)&g_sum)     = 0;
            *((volatile unsigned int*)&g_count) = 0u;
            __threadfence();
        }
    }
}

extern "C" void kernel_launch(void* const* d_in, const int* in_sizes, int n_in,
                              void* d_out, int out_size)
{
    const float* pred = (const float*)d_in[0];
    const float* y    = (const float*)d_in[1];
    float* out        = (float*)d_out;

    dim3 grid(N_TP, N_COL);
    tau_fused_kernel<<<grid, TILE>>>(pred, y, out);
}